// round 1
// baseline (speedup 1.0000x reference)
#include <cuda_runtime.h>
#include <cstdint>

// InstantNGP fused: hash-grid encode (L=16, F=2, T=2^19) + MLP 32->64->64->3
// One thread per point. Weights in shared memory, broadcast float4 reads.
// Encoding fused into layer-0 accumulation (no enc[] array).

namespace {

constexpr int S_DIM   = 1024;
constexpr int NPTS    = S_DIM * S_DIM;
constexpr int LVLS    = 16;
constexpr int TBL     = 1 << 19;
constexpr int HID     = 64;
constexpr int ENC_D   = 32;
constexpr int THREADS = 256;

__global__ __launch_bounds__(THREADS) void ngp_fused_kernel(
    const float2* __restrict__ xy,        // (NPTS, 2)
    const float2* __restrict__ tab,       // (L, T, 2) as float2
    const float*  __restrict__ W0,        // (32, 64)
    const float*  __restrict__ W1,        // (64, 64)
    const float*  __restrict__ W2,        // (64, 3)
    float*        __restrict__ out)       // (3, S, S) flattened
{
    __shared__ float4 sW0[ENC_D * HID / 4];   //  8 KB
    __shared__ float4 sW1[HID * HID / 4];     // 16 KB
    __shared__ float  sW2[HID * 3];           // 768 B

    {
        const float4* gW0 = reinterpret_cast<const float4*>(W0);
        const float4* gW1 = reinterpret_cast<const float4*>(W1);
        for (int i = threadIdx.x; i < ENC_D * HID / 4; i += THREADS) sW0[i] = gW0[i];
        for (int i = threadIdx.x; i < HID * HID / 4;   i += THREADS) sW1[i] = gW1[i];
        for (int i = threadIdx.x; i < HID * 3;         i += THREADS) sW2[i] = W2[i];
    }
    __syncthreads();

    const int pid = blockIdx.x * THREADS + threadIdx.x;
    const float2 p = xy[pid];
    const float c0 = p.x;   // reference: coordinate dim 0
    const float c1 = p.y;   // coordinate dim 1

    float h0[HID];
#pragma unroll
    for (int j = 0; j < HID; j++) h0[j] = 0.0f;

    // floor(16 * 1.5^l), exact in fp32 for l<16
    const int res_tab[LVLS] = {16, 24, 36, 54, 81, 121, 182, 273,
                               410, 615, 922, 1383, 2075, 3113, 4670, 7006};

#pragma unroll
    for (int l = 0; l < LVLS; l++) {
        const int res = res_tab[l];
        const bool dense = ((long long)(res + 1) * (res + 1) <= (long long)TBL);

        const float fres = (float)res;
        const float px = c0 * fres;
        const float py = c1 * fres;
        const float fx = floorf(px);
        const float fy = floorf(py);
        const float wx = px - fx;
        const float wy = py - fy;
        const int ix = (int)fx;
        const int iy = (int)fy;

        int i00, i01, i10, i11;
        if (dense) {
            const int r1 = res + 1;
            i00 = ix + iy * r1;        // corner (ix,   iy  )
            i01 = i00 + r1;            // corner (ix,   iy+1)
            i10 = i00 + 1;             // corner (ix+1, iy  )
            i11 = i01 + 1;             // corner (ix+1, iy+1)
        } else {
            const uint32_t P = 2654435761u;
            const uint32_t ux = (uint32_t)ix;
            const uint32_t uy = (uint32_t)iy;
            const uint32_t hy0 = uy * P;
            const uint32_t hy1 = (uy + 1u) * P;
            i00 = (int)((ux        ^ hy0) & (uint32_t)(TBL - 1));
            i01 = (int)((ux        ^ hy1) & (uint32_t)(TBL - 1));
            i10 = (int)(((ux + 1u) ^ hy0) & (uint32_t)(TBL - 1));
            i11 = (int)(((ux + 1u) ^ hy1) & (uint32_t)(TBL - 1));
        }

        const float2* lt = tab + (size_t)l * TBL;
        const float2 a00 = __ldg(lt + i00);
        const float2 a01 = __ldg(lt + i01);
        const float2 a10 = __ldg(lt + i10);
        const float2 a11 = __ldg(lt + i11);

        const float w00 = (1.0f - wx) * (1.0f - wy);
        const float w01 = (1.0f - wx) * wy;
        const float w10 = wx * (1.0f - wy);
        const float w11 = wx * wy;

        const float f0 = a00.x * w00 + a01.x * w01 + a10.x * w10 + a11.x * w11;
        const float f1 = a00.y * w00 + a01.y * w01 + a10.y * w10 + a11.y * w11;

        // Fused layer-0 accumulation: h0 += f0 * W0[2l,:] + f1 * W0[2l+1,:]
#pragma unroll
        for (int j = 0; j < HID / 4; j++) {
            const float4 wa = sW0[(2 * l)     * (HID / 4) + j];
            const float4 wb = sW0[(2 * l + 1) * (HID / 4) + j];
            h0[4 * j + 0] += f0 * wa.x + f1 * wb.x;
            h0[4 * j + 1] += f0 * wa.y + f1 * wb.y;
            h0[4 * j + 2] += f0 * wa.z + f1 * wb.z;
            h0[4 * j + 3] += f0 * wa.w + f1 * wb.w;
        }
    }

    // ReLU layer 0
#pragma unroll
    for (int j = 0; j < HID; j++) h0[j] = fmaxf(h0[j], 0.0f);

    // Layer 1: h1 = relu(h0 @ W1)
    float h1[HID];
#pragma unroll
    for (int j = 0; j < HID; j++) h1[j] = 0.0f;

#pragma unroll
    for (int k = 0; k < HID; k++) {
        const float v = h0[k];
#pragma unroll
        for (int j = 0; j < HID / 4; j++) {
            const float4 w = sW1[k * (HID / 4) + j];
            h1[4 * j + 0] += v * w.x;
            h1[4 * j + 1] += v * w.y;
            h1[4 * j + 2] += v * w.z;
            h1[4 * j + 3] += v * w.w;
        }
    }
#pragma unroll
    for (int j = 0; j < HID; j++) h1[j] = fmaxf(h1[j], 0.0f);

    // Layer 2: out = h1 @ W2  (64 x 3)
    float o0 = 0.0f, o1 = 0.0f, o2 = 0.0f;
#pragma unroll
    for (int k = 0; k < HID; k++) {
        const float v = h1[k];
        o0 += v * sW2[k * 3 + 0];
        o1 += v * sW2[k * 3 + 1];
        o2 += v * sW2[k * 3 + 2];
    }

    out[0 * NPTS + pid] = o0;
    out[1 * NPTS + pid] = o1;
    out[2 * NPTS + pid] = o2;
}

}  // namespace

extern "C" void kernel_launch(void* const* d_in, const int* in_sizes, int n_in,
                              void* d_out, int out_size) {
    (void)in_sizes; (void)n_in; (void)out_size;
    const float2* xy  = (const float2*)d_in[0];
    const float2* tab = (const float2*)d_in[1];
    const float*  W0  = (const float*)d_in[2];
    const float*  W1  = (const float*)d_in[3];
    const float*  W2  = (const float*)d_in[4];
    float* out = (float*)d_out;

    ngp_fused_kernel<<<NPTS / THREADS, THREADS>>>(xy, tab, W0, W1, W2, out);
}

// round 4
// speedup vs baseline: 5.2791x; 5.2791x over previous
#include <cuda_runtime.h>
#include <cstdint>

// InstantNGP: hash-grid encode + MLP 32->64->64->3 via warp-level tf32 mma.sync
// (baseline PTX, works on compute_103 without 'a' features).
//
// Per warp-tile (16 points):
//   encode (2 thr/point, even/odd levels) -> tf32 SMEM tile (16x32)
//   mma.sync m16n8k8 layer0 (K=32, N=64)  -> relu -> SMEM (16x64)
//   mma.sync layer1 (K=64, N=64)          -> epilogue 64x3 from C frags + shfl reduce
// Weights staged once per CTA in fragment order (LDS.64 per B frag).

namespace {

constexpr int S_DIM   = 1024;
constexpr int NPTS    = S_DIM * S_DIM;
constexpr int TBL     = 1 << 19;

constexpr int WARPS   = 4;
constexpr int THREADS = WARPS * 32;
constexpr int TILE    = 16;               // points per warp-tile
constexpr int TPW     = 8;                // tiles per warp
constexpr int PPW     = TILE * TPW;       // 128 points per warp
constexpr int GRID    = NPTS / (PPW * WARPS);   // 2048
constexpr int BSTRIDE = 68;               // floats per scratch row (conflict-free A reads)

__device__ __forceinline__ uint32_t tf32_rna(float x) {
    uint32_t r;
    asm("cvt.rna.tf32.f32 %0, %1;" : "=r"(r) : "f"(x));
    return r;
}

__device__ __forceinline__ void mma8(float* d,
                                     uint32_t a0, uint32_t a1, uint32_t a2, uint32_t a3,
                                     uint32_t b0, uint32_t b1) {
    asm volatile(
        "mma.sync.aligned.m16n8k8.row.col.f32.tf32.tf32.f32 "
        "{%0,%1,%2,%3},{%4,%5,%6,%7},{%8,%9},{%0,%1,%2,%3};"
        : "+f"(d[0]), "+f"(d[1]), "+f"(d[2]), "+f"(d[3])
        : "r"(a0), "r"(a1), "r"(a2), "r"(a3), "r"(b0), "r"(b1));
}

__global__ __launch_bounds__(THREADS) void ngp_mma_kernel(
    const float2* __restrict__ xy,
    const float2* __restrict__ tab,
    const float*  __restrict__ W0,     // (32, 64) [k][n]
    const float*  __restrict__ W1,     // (64, 64) [k][n]
    const float*  __restrict__ W2,     // (64, 3)
    float*        __restrict__ out)    // (3, S, S)
{
    __shared__ uint2    w0f[4 * 8 * 32];             //  8 KB  B frags layer0
    __shared__ uint2    w1f[8 * 8 * 32];             // 16 KB  B frags layer1
    __shared__ float    w2s[64 * 3];
    __shared__ uint32_t scratch[WARPS][TILE * BSTRIDE];  // ~17 KB

    const int tid = threadIdx.x;

    // ---- stage weights in fragment order (once per CTA) ----
    for (int i = tid; i < 4 * 8 * 32; i += THREADS) {
        const int k = i >> 8, nt = (i >> 5) & 7, ln = i & 31;
        const int t = ln & 3, g = ln >> 2;
        w0f[i] = make_uint2(tf32_rna(W0[(8 * k + t) * 64 + nt * 8 + g]),
                            tf32_rna(W0[(8 * k + t + 4) * 64 + nt * 8 + g]));
    }
    for (int i = tid; i < 8 * 8 * 32; i += THREADS) {
        const int k = i >> 8, nt = (i >> 5) & 7, ln = i & 31;
        const int t = ln & 3, g = ln >> 2;
        w1f[i] = make_uint2(tf32_rna(W1[(8 * k + t) * 64 + nt * 8 + g]),
                            tf32_rna(W1[(8 * k + t + 4) * 64 + nt * 8 + g]));
    }
    for (int i = tid; i < 64 * 3; i += THREADS) w2s[i] = W2[i];
    __syncthreads();

    const int wid  = tid >> 5;
    const int lane = tid & 31;
    const int t    = lane & 3;          // threadIDInGroup
    const int g    = lane >> 2;         // groupID (row within 8)
    const int h    = lane >> 4;         // level parity for encode
    const int pl   = lane & 15;         // point within tile for encode
    uint32_t* buf  = scratch[wid];
    const int wg   = blockIdx.x * WARPS + wid;

    // floor(16 * 1.5^l): even levels / odd levels
    const int res_e[8] = {16, 36, 81, 182, 410, 922, 2075, 4670};
    const int res_o[8] = {24, 54, 121, 273, 615, 1383, 3113, 7006};

    for (int tile = 0; tile < TPW; tile++) {
        const int tb = wg * PPW + tile * TILE;
        __syncwarp();

        // ---- encode: point pl, levels 2*lp + h ----
        const float2 p = __ldg(&xy[tb + pl]);
        const float c0 = p.x, c1 = p.y;
#pragma unroll
        for (int lp = 0; lp < 8; lp++) {
            const int res   = h ? res_o[lp] : res_e[lp];
            const int level = 2 * lp + h;
            const bool dense = (lp < 5);   // levels 0..9 dense, 10..15 hashed

            const float fres = (float)res;
            const float px = c0 * fres;
            const float py = c1 * fres;
            const float fx = floorf(px);
            const float fy = floorf(py);
            const float wx = px - fx;
            const float wy = py - fy;
            const int ix = (int)fx;
            const int iy = (int)fy;

            int i00, i01, i10, i11;
            if (dense) {
                const int r1 = res + 1;
                i00 = ix + iy * r1;
                i01 = i00 + r1;
                i10 = i00 + 1;
                i11 = i01 + 1;
            } else {
                const uint32_t P = 2654435761u;
                const uint32_t ux = (uint32_t)ix;
                const uint32_t uy = (uint32_t)iy;
                const uint32_t hy0 = uy * P;
                const uint32_t hy1 = (uy + 1u) * P;
                i00 = (int)((ux        ^ hy0) & (uint32_t)(TBL - 1));
                i01 = (int)((ux        ^ hy1) & (uint32_t)(TBL - 1));
                i10 = (int)(((ux + 1u) ^ hy0) & (uint32_t)(TBL - 1));
                i11 = (int)(((ux + 1u) ^ hy1) & (uint32_t)(TBL - 1));
            }

            const float2* lt = tab + (size_t)level * TBL;
            const float2 a00 = __ldg(lt + i00);
            const float2 a01 = __ldg(lt + i01);
            const float2 a10 = __ldg(lt + i10);
            const float2 a11 = __ldg(lt + i11);

            const float w00 = (1.0f - wx) * (1.0f - wy);
            const float w01 = (1.0f - wx) * wy;
            const float w10 = wx * (1.0f - wy);
            const float w11 = wx * wy;

            const float f0 = a00.x * w00 + a01.x * w01 + a10.x * w10 + a11.x * w11;
            const float f1 = a00.y * w00 + a01.y * w01 + a10.y * w10 + a11.y * w11;

            *reinterpret_cast<uint2*>(&buf[pl * BSTRIDE + 4 * lp + 2 * h]) =
                make_uint2(tf32_rna(f0), tf32_rna(f1));
        }
        __syncwarp();

        // ---- layer 0: (16x32) @ (32x64), m16n8k8, 4 K-steps x 8 N-tiles ----
        float C[8][4];
#pragma unroll
        for (int nt = 0; nt < 8; nt++)
#pragma unroll
            for (int j = 0; j < 4; j++) C[nt][j] = 0.0f;

#pragma unroll
        for (int k = 0; k < 4; k++) {
            const uint32_t a0 = buf[g * BSTRIDE + 8 * k + t];
            const uint32_t a1 = buf[(g + 8) * BSTRIDE + 8 * k + t];
            const uint32_t a2 = buf[g * BSTRIDE + 8 * k + t + 4];
            const uint32_t a3 = buf[(g + 8) * BSTRIDE + 8 * k + t + 4];
#pragma unroll
            for (int nt = 0; nt < 8; nt++) {
                const uint2 b = w0f[(k * 8 + nt) * 32 + lane];
                mma8(C[nt], a0, a1, a2, a3, b.x, b.y);
            }
        }
        __syncwarp();

        // ---- relu + store h0 (16x64, tf32) ----
#pragma unroll
        for (int nt = 0; nt < 8; nt++) {
            const int col = nt * 8 + 2 * t;
            *reinterpret_cast<uint2*>(&buf[g * BSTRIDE + col]) =
                make_uint2(tf32_rna(fmaxf(C[nt][0], 0.0f)),
                           tf32_rna(fmaxf(C[nt][1], 0.0f)));
            *reinterpret_cast<uint2*>(&buf[(g + 8) * BSTRIDE + col]) =
                make_uint2(tf32_rna(fmaxf(C[nt][2], 0.0f)),
                           tf32_rna(fmaxf(C[nt][3], 0.0f)));
        }
        __syncwarp();

        // ---- layer 1: (16x64) @ (64x64), 8 K-steps x 8 N-tiles ----
        float C1[8][4];
#pragma unroll
        for (int nt = 0; nt < 8; nt++)
#pragma unroll
            for (int j = 0; j < 4; j++) C1[nt][j] = 0.0f;

#pragma unroll
        for (int k = 0; k < 8; k++) {
            const uint32_t a0 = buf[g * BSTRIDE + 8 * k + t];
            const uint32_t a1 = buf[(g + 8) * BSTRIDE + 8 * k + t];
            const uint32_t a2 = buf[g * BSTRIDE + 8 * k + t + 4];
            const uint32_t a3 = buf[(g + 8) * BSTRIDE + 8 * k + t + 4];
#pragma unroll
            for (int nt = 0; nt < 8; nt++) {
                const uint2 b = w1f[(k * 8 + nt) * 32 + lane];
                mma8(C1[nt], a0, a1, a2, a3, b.x, b.y);
            }
        }

        // ---- epilogue: relu + (64x3) from C frags, shfl reduce over t ----
        float acc[2][3] = {{0.f, 0.f, 0.f}, {0.f, 0.f, 0.f}};
#pragma unroll
        for (int nt = 0; nt < 8; nt++) {
            const int cA = nt * 8 + 2 * t;
            const int cB = cA + 1;
            const float vA0 = fmaxf(C1[nt][0], 0.0f);
            const float vB0 = fmaxf(C1[nt][1], 0.0f);
            const float vA1 = fmaxf(C1[nt][2], 0.0f);
            const float vB1 = fmaxf(C1[nt][3], 0.0f);
#pragma unroll
            for (int j = 0; j < 3; j++) {
                acc[0][j] += vA0 * w2s[cA * 3 + j] + vB0 * w2s[cB * 3 + j];
                acc[1][j] += vA1 * w2s[cA * 3 + j] + vB1 * w2s[cB * 3 + j];
            }
        }
#pragma unroll
        for (int r = 0; r < 2; r++)
#pragma unroll
            for (int j = 0; j < 3; j++) {
                float v = acc[r][j];
                v += __shfl_xor_sync(0xffffffffu, v, 1);
                v += __shfl_xor_sync(0xffffffffu, v, 2);
                acc[r][j] = v;
            }
        if (t == 0) {
#pragma unroll
            for (int r = 0; r < 2; r++) {
                const int pid = tb + g + 8 * r;
#pragma unroll
                for (int j = 0; j < 3; j++) out[j * NPTS + pid] = acc[r][j];
            }
        }
    }
}

}  // namespace

extern "C" void kernel_launch(void* const* d_in, const int* in_sizes, int n_in,
                              void* d_out, int out_size) {
    (void)in_sizes; (void)n_in; (void)out_size;
    const float2* xy  = (const float2*)d_in[0];
    const float2* tab = (const float2*)d_in[1];
    const float*  W0  = (const float*)d_in[2];
    const float*  W1  = (const float*)d_in[3];
    const float*  W2  = (const float*)d_in[4];
    float* out = (float*)d_out;

    ngp_mma_kernel<<<GRID, THREADS>>>(xy, tab, W0, W1, W2, out);
}